// round 5
// baseline (speedup 1.0000x reference)
#include <cuda_runtime.h>

#define BATCH 8
#define N_SEQ 1024
#define CDIM  256
#define RREL  16

// Scratch (device globals — no allocation allowed)
__device__ __align__(16) float g_Gt[CDIM * CDIM];        // Gt[m][k] = sum_c Wq[c][k]*Wk[c][m]
__device__ __align__(16) float g_wu[CDIM];               // Wq^T @ b_k
__device__ __align__(16) float g_wv[CDIM];               // Wk^T @ b_q
__device__ float g_cst;                                  // b_q . b_k
__device__ __align__(16) float g_A[BATCH * N_SEQ * CDIM];// Q @ G  (8 MB)
__device__ __align__(16) float g_u[BATCH * N_SEQ];
__device__ __align__(16) float g_v[BATCH * N_SEQ];

// ---------------------------------------------------------------------------
// prep_w: blocks 0..255 compute Gt; block 256 computes wu/wv/cst.
// (merged so the launch cycle is 4 kernels -> ncu capture index 3 = main_fused)
// ---------------------------------------------------------------------------
__global__ void prep_w(const float* __restrict__ Wq, const float* __restrict__ Wk,
                       const float* __restrict__ bq, const float* __restrict__ bk) {
    int tid = threadIdx.x;
    if (blockIdx.x == 256) {
        float su = 0.f, sv = 0.f;
        for (int c = 0; c < CDIM; c++) {
            su += Wq[c * CDIM + tid] * bk[c];
            sv += Wk[c * CDIM + tid] * bq[c];
        }
        g_wu[tid] = su;
        g_wv[tid] = sv;
        __shared__ float red[256];
        red[tid] = bq[tid] * bk[tid];
        __syncthreads();
        for (int s = 128; s > 0; s >>= 1) {
            if (tid < s) red[tid] += red[tid + s];
            __syncthreads();
        }
        if (tid == 0) g_cst = red[0];
        return;
    }
    int bx = blockIdx.x;
    int mt = bx >> 4;
    int kt = bx & 15;
    int tm = tid >> 4;
    int tk = tid & 15;
    int lc = tid >> 4;
    int li = tid & 15;

    __shared__ float sq[16][16];
    __shared__ float sk[16][16];

    float acc = 0.f;
    for (int c0 = 0; c0 < CDIM; c0 += 16) {
        sq[lc][li] = Wq[(c0 + lc) * CDIM + kt * 16 + li];
        sk[lc][li] = Wk[(c0 + lc) * CDIM + mt * 16 + li];
        __syncthreads();
#pragma unroll
        for (int cc = 0; cc < 16; cc++)
            acc += sq[cc][tk] * sk[cc][tm];
        __syncthreads();
    }
    g_Gt[(mt * 16 + tm) * CDIM + kt * 16 + tk] = acc;
}

// ---------------------------------------------------------------------------
// compute_uv: u[row] = Q[row].wu ; v[row] = K[row].wv  (rows = B*N = 8192)
// ---------------------------------------------------------------------------
__global__ void compute_uv(const float* __restrict__ Q, const float* __restrict__ K) {
    int warp = threadIdx.x >> 5;
    int lane = threadIdx.x & 31;
    int row = blockIdx.x * 8 + warp;
    const float* qr = Q + (size_t)row * CDIM;
    const float* kr = K + (size_t)row * CDIM;
    float au = 0.f, av = 0.f;
#pragma unroll
    for (int t = 0; t < 8; t++) {
        int c = lane + t * 32;
        au += qr[c] * g_wu[c];
        av += kr[c] * g_wv[c];
    }
#pragma unroll
    for (int o = 16; o > 0; o >>= 1) {
        au += __shfl_down_sync(0xffffffffu, au, o);
        av += __shfl_down_sync(0xffffffffu, av, o);
    }
    if (lane == 0) {
        g_u[row] = au;
        g_v[row] = av;
    }
}

// ---------------------------------------------------------------------------
// gemm_A: A[row, m] = sum_k Q[row,k] * Gt[m,k]   (8192 x 256 x 256, NT)
// ---------------------------------------------------------------------------
__global__ __launch_bounds__(256, 2) void gemm_A(const float* __restrict__ Q) {
    int mt = blockIdx.x;
    int rt = blockIdx.y;
    int tid = threadIdx.x;
    int tx = tid & 15;
    int ty = tid >> 4;
    int lrow = tid >> 2;
    int lk = (tid & 3) << 2;

    __shared__ __align__(16) float As[2][16][128];
    __shared__ __align__(16) float Bs[2][16][64];

    const float* Ap = Q + (size_t)rt * 128 * CDIM;
    const float* Bp = g_Gt + (size_t)mt * 64 * CDIM;

    float4 ra0, ra1, rb0;

    auto ldg_stage = [&](int k0) {
        ra0 = *(const float4*)(Ap + (size_t)lrow * CDIM + k0 + lk);
        ra1 = *(const float4*)(Ap + (size_t)(64 + lrow) * CDIM + k0 + lk);
        rb0 = *(const float4*)(Bp + (size_t)lrow * CDIM + k0 + lk);
    };
    auto sts_stage = [&](int buf) {
        As[buf][lk + 0][lrow] = ra0.x; As[buf][lk + 1][lrow] = ra0.y;
        As[buf][lk + 2][lrow] = ra0.z; As[buf][lk + 3][lrow] = ra0.w;
        As[buf][lk + 0][64 + lrow] = ra1.x; As[buf][lk + 1][64 + lrow] = ra1.y;
        As[buf][lk + 2][64 + lrow] = ra1.z; As[buf][lk + 3][64 + lrow] = ra1.w;
        Bs[buf][lk + 0][lrow] = rb0.x; Bs[buf][lk + 1][lrow] = rb0.y;
        Bs[buf][lk + 2][lrow] = rb0.z; Bs[buf][lk + 3][lrow] = rb0.w;
    };

    float acc[8][4] = {};

    ldg_stage(0);
    sts_stage(0);
    __syncthreads();

    for (int s = 0; s < 16; s++) {
        int cur = s & 1;
        if (s < 15) ldg_stage((s + 1) * 16);
#pragma unroll
        for (int kk = 0; kk < 16; kk++) {
            float4 a0 = *(const float4*)&As[cur][kk][ty * 8];
            float4 a1 = *(const float4*)&As[cur][kk][ty * 8 + 4];
            float4 b0 = *(const float4*)&Bs[cur][kk][tx * 4];
            float av[8] = {a0.x, a0.y, a0.z, a0.w, a1.x, a1.y, a1.z, a1.w};
            float bv[4] = {b0.x, b0.y, b0.z, b0.w};
#pragma unroll
            for (int ii = 0; ii < 8; ii++)
#pragma unroll
                for (int jj = 0; jj < 4; jj++)
                    acc[ii][jj] += av[ii] * bv[jj];
        }
        if (s < 15) {
            sts_stage(cur ^ 1);
            __syncthreads();
        }
    }

    int row = rt * 128 + ty * 8;
    int m = mt * 64 + tx * 4;
#pragma unroll
    for (int ii = 0; ii < 8; ii++) {
        float4 o = {acc[ii][0], acc[ii][1], acc[ii][2], acc[ii][3]};
        *(float4*)&g_A[(size_t)(row + ii) * CDIM + m] = o;
    }
}

// ---------------------------------------------------------------------------
// main_fused v5: 128(i) x 64(j) tile, 8x8 micro, 128 threads, occ-3.
// Per kk: 4 LDS.128 feed 64 FFMA -> FFMA dominates issue stream (the R4 fix).
//   scores = (A[b,i,:] . Key[b,j,:] + u[i] + v[j] + cst) / 16
//   out[b,r,i,j] = scores * R_map[i,j,r]
// grid (8 batch <- fastest for R_map L2 reuse, 128 tiles), 128 threads
// ---------------------------------------------------------------------------
__global__ __launch_bounds__(128, 3) void main_fused(const float* __restrict__ Key,
                                                     const float* __restrict__ Rmap,
                                                     float* __restrict__ out) {
    int b = blockIdx.x;
    int tile = blockIdx.y;        // 0..127
    int it = tile >> 4;           // 0..7   (128 i-rows each)
    int jt = tile & 15;           // 0..15  (64 j-cols each)
    int tid = threadIdx.x;        // 0..127
    int tx = tid & 7;             // j dir (8 each)
    int ty = tid >> 3;            // i dir (8 each, 16 slots)

    __shared__ __align__(16) float As[2][16][128];  // [buf][k][i]
    __shared__ __align__(16) float Bs[2][16][64];   // [buf][k][j]

    const float* Ap = g_A + ((size_t)b * N_SEQ + it * 128) * CDIM;
    const float* Bp = Key + ((size_t)b * N_SEQ + jt * 64) * CDIM;

    // loader mapping
    int arow = tid;               // 0..127 : one A row per thread, 16 k each
    int brow = tid & 63;          // 0..63
    int bko = (tid >> 6) << 3;    // 0 or 8 : k-half for B

    float4 ra[4], rb[2];

    auto ldg_stage = [&](int k0) {
#pragma unroll
        for (int q = 0; q < 4; q++)
            ra[q] = *(const float4*)(Ap + (size_t)arow * CDIM + k0 + q * 4);
        rb[0] = *(const float4*)(Bp + (size_t)brow * CDIM + k0 + bko);
        rb[1] = *(const float4*)(Bp + (size_t)brow * CDIM + k0 + bko + 4);
    };
    auto sts_stage = [&](int buf) {
#pragma unroll
        for (int q = 0; q < 4; q++) {
            As[buf][q * 4 + 0][arow] = ra[q].x;
            As[buf][q * 4 + 1][arow] = ra[q].y;
            As[buf][q * 4 + 2][arow] = ra[q].z;
            As[buf][q * 4 + 3][arow] = ra[q].w;
        }
        Bs[buf][bko + 0][brow] = rb[0].x; Bs[buf][bko + 1][brow] = rb[0].y;
        Bs[buf][bko + 2][brow] = rb[0].z; Bs[buf][bko + 3][brow] = rb[0].w;
        Bs[buf][bko + 4][brow] = rb[1].x; Bs[buf][bko + 5][brow] = rb[1].y;
        Bs[buf][bko + 6][brow] = rb[1].z; Bs[buf][bko + 7][brow] = rb[1].w;
    };

    float acc[8][8] = {};

    ldg_stage(0);
    sts_stage(0);
    __syncthreads();

    for (int s = 0; s < 16; s++) {
        int cur = s & 1;
        if (s < 15) ldg_stage((s + 1) * 16);
#pragma unroll
        for (int kk = 0; kk < 16; kk++) {
            float4 a0 = *(const float4*)&As[cur][kk][ty * 8];
            float4 a1 = *(const float4*)&As[cur][kk][ty * 8 + 4];
            float4 b0 = *(const float4*)&Bs[cur][kk][tx * 8];
            float4 b1 = *(const float4*)&Bs[cur][kk][tx * 8 + 4];
            float av[8] = {a0.x, a0.y, a0.z, a0.w, a1.x, a1.y, a1.z, a1.w};
            float bv[8] = {b0.x, b0.y, b0.z, b0.w, b1.x, b1.y, b1.z, b1.w};
#pragma unroll
            for (int ii = 0; ii < 8; ii++)
#pragma unroll
                for (int jj = 0; jj < 8; jj++)
                    acc[ii][jj] += av[ii] * bv[jj];
        }
        if (s < 15) {
            sts_stage(cur ^ 1);    // ping-pong: single barrier per stage
            __syncthreads();
        }
    }

    // ---- epilogue: finalize scores ----
    int i0 = it * 128 + ty * 8;
    int j0 = jt * 64 + tx * 8;
    float cst = g_cst;
    float4 u0 = *(const float4*)&g_u[b * N_SEQ + i0];
    float4 u1 = *(const float4*)&g_u[b * N_SEQ + i0 + 4];
    float4 v0 = *(const float4*)&g_v[b * N_SEQ + j0];
    float4 v1 = *(const float4*)&g_v[b * N_SEQ + j0 + 4];
    float uu[8] = {u0.x, u0.y, u0.z, u0.w, u1.x, u1.y, u1.z, u1.w};
    float vv[8] = {v0.x, v0.y, v0.z, v0.w, v1.x, v1.y, v1.z, v1.w};

#pragma unroll
    for (int ii = 0; ii < 8; ii++)
#pragma unroll
        for (int jj = 0; jj < 8; jj++)
            acc[ii][jj] = (acc[ii][jj] + uu[ii] + vv[jj] + cst) * 0.0625f;

    // ---- relation-mask multiply + streaming store ----
    const size_t NN = (size_t)N_SEQ * N_SEQ;
#pragma unroll
    for (int ii = 0; ii < 8; ii++) {
        int i = i0 + ii;
        const float* rp = Rmap + ((size_t)i * N_SEQ + j0) * RREL;
        float* op = out + (size_t)(b * RREL) * NN + (size_t)i * N_SEQ + j0;
#pragma unroll
        for (int rq = 0; rq < 4; rq++) {
            float qv[32];
#pragma unroll
            for (int jj = 0; jj < 8; jj++) {
                float4 t = *(const float4*)(rp + jj * RREL + rq * 4);
                qv[jj * 4 + 0] = t.x; qv[jj * 4 + 1] = t.y;
                qv[jj * 4 + 2] = t.z; qv[jj * 4 + 3] = t.w;
            }
#pragma unroll
            for (int rr = 0; rr < 4; rr++) {
                int r = rq * 4 + rr;
                float4 o0, o1;
                o0.x = acc[ii][0] * qv[0 * 4 + rr];
                o0.y = acc[ii][1] * qv[1 * 4 + rr];
                o0.z = acc[ii][2] * qv[2 * 4 + rr];
                o0.w = acc[ii][3] * qv[3 * 4 + rr];
                o1.x = acc[ii][4] * qv[4 * 4 + rr];
                o1.y = acc[ii][5] * qv[5 * 4 + rr];
                o1.z = acc[ii][6] * qv[6 * 4 + rr];
                o1.w = acc[ii][7] * qv[7 * 4 + rr];
                float* dst = op + (size_t)r * NN;
                __stcs((float4*)dst, o0);
                __stcs((float4*)(dst + 4), o1);
            }
        }
    }
}

// ---------------------------------------------------------------------------
extern "C" void kernel_launch(void* const* d_in, const int* in_sizes, int n_in,
                              void* d_out, int out_size) {
    const float* Q    = (const float*)d_in[0];
    const float* K    = (const float*)d_in[1];
    const float* Wq   = (const float*)d_in[2];
    const float* bq   = (const float*)d_in[3];
    const float* Wk   = (const float*)d_in[4];
    const float* bk   = (const float*)d_in[5];
    const float* Rmap = (const float*)d_in[6];
    float* out = (float*)d_out;

    prep_w<<<257, 256>>>(Wq, Wk, bq, bk);
    compute_uv<<<1024, 256>>>(Q, K);
    gemm_A<<<dim3(4, 64), 256>>>(Q);
    main_fused<<<dim3(8, 128), 128>>>(K, Rmap, out);
}